// round 1
// baseline (speedup 1.0000x reference)
#include <cuda_runtime.h>
#include <cuda_fp16.h>
#include <cstdint>

#define M_TOK 64
#define N_OUT 8192
#define K_IN  8192
#define NG    64          // number of K groups (8192/128)
#define BN    64          // N columns per block
#define BK    128         // K per chunk == quant group size
#define LDK   136         // smem row stride in halves (128 + 8 pad -> conflict-free ldmatrix)
#define NTHREADS 256

// x pre-converted to fp16 (1 MB, L2-resident)
__device__ __half g_xh[M_TOK * K_IN];

__global__ void convert_x_kernel(const float* __restrict__ x) {
    int i = (blockIdx.x * blockDim.x + threadIdx.x) * 2;
    float2 v = *reinterpret_cast<const float2*>(x + i);
    *reinterpret_cast<__half2*>(g_xh + i) = __floats2half2_rn(v.x, v.y);
}

__device__ __forceinline__ void ldsm4(uint32_t& r0, uint32_t& r1, uint32_t& r2, uint32_t& r3,
                                      uint32_t a) {
    asm volatile("ldmatrix.sync.aligned.m8n8.x4.shared.b16 {%0,%1,%2,%3}, [%4];"
                 : "=r"(r0), "=r"(r1), "=r"(r2), "=r"(r3) : "r"(a));
}

__device__ __forceinline__ void mma_16816(float c[4],
                                          uint32_t a0, uint32_t a1, uint32_t a2, uint32_t a3,
                                          uint32_t b0, uint32_t b1) {
    asm volatile("mma.sync.aligned.m16n8k16.row.col.f32.f16.f16.f32 "
                 "{%0,%1,%2,%3}, {%4,%5,%6,%7}, {%8,%9}, {%0,%1,%2,%3};"
                 : "+f"(c[0]), "+f"(c[1]), "+f"(c[2]), "+f"(c[3])
                 : "r"(a0), "r"(a1), "r"(a2), "r"(a3), "r"(b0), "r"(b1));
}

__global__ void __launch_bounds__(NTHREADS, 1)
woq_gemm_kernel(const int* __restrict__ qw,      // [N_OUT][K_IN] int32, values 0..15
                const float* __restrict__ sz,    // [NG][N_OUT][2] (scale, zero_point)
                float* __restrict__ out)         // [M_TOK][N_OUT]
{
    __shared__ __half As[M_TOK * LDK];  // x tile   [64][BK]
    __shared__ __half Bs[BN * LDK];     // w tile   [64][BK] (dequantized fp16)

    const int tid  = threadIdx.x;
    const int lane = tid & 31;
    const int warp = tid >> 5;
    const int wm   = warp & 3;   // m-tile of 16 rows
    const int wn   = warp >> 2;  // n-half of 32 cols
    const int nblk = blockIdx.x * BN;

    float acc[4][4];
    #pragma unroll
    for (int i = 0; i < 4; ++i)
        #pragma unroll
        for (int j = 0; j < 4; ++j) acc[i][j] = 0.f;

    const uint32_t as_b = (uint32_t)__cvta_generic_to_shared(As);
    const uint32_t bs_b = (uint32_t)__cvta_generic_to_shared(Bs);

    // ldmatrix lane addressing (precomputed row parts, +kk*32 bytes per k-step)
    const uint32_t a_off  = as_b + 2u * ((wm * 16 + (lane & 15)) * LDK + (lane >> 4) * 8);
    const uint32_t b_off0 = bs_b + 2u * ((wn * 32 + (lane & 7) + ((lane >> 4) << 3)) * LDK
                                         + ((lane >> 3) & 1) * 8);
    const uint32_t b_off1 = b_off0 + 2u * 16 * LDK;

    int4 wq[8];   // staged int32 weights: 32 q values/thread/chunk
    int4 xr[4];   // staged x halves:      32 halves/thread/chunk

    // ---- prologue: load chunk 0 ----
    #pragma unroll
    for (int it = 0; it < 8; ++it)
        wq[it] = *reinterpret_cast<const int4*>(
            qw + (size_t)(nblk + it * 8 + warp) * K_IN + lane * 4);
    #pragma unroll
    for (int it = 0; it < 4; ++it)
        xr[it] = *reinterpret_cast<const int4*>(
            g_xh + (size_t)(it * 16 + (tid >> 4)) * K_IN + (tid & 15) * 8);

    const __half2 k1032 = __floats2half2_rn(1032.f, 1032.f);  // exact in fp16

    for (int c = 0; c < NG; ++c) {
        // ---- stage x tile ----
        #pragma unroll
        for (int it = 0; it < 4; ++it)
            *reinterpret_cast<int4*>(&As[(it * 16 + (tid >> 4)) * LDK + (tid & 15) * 8]) = xr[it];

        // ---- dequant + stage w tile ----
        #pragma unroll
        for (int it = 0; it < 8; ++it) {
            const int nloc = it * 8 + warp;
            float2 s_z = *reinterpret_cast<const float2*>(
                sz + 2u * ((size_t)c * N_OUT + nblk + nloc));
            const __half2 s2 = __half2half2(__float2half_rn(s_z.x));
            const __half2 z2 = __half2half2(__float2half_rn(s_z.y));
            const int4 q = wq[it];
            // 0x6400|q bitcasts to fp16 value (1024+q) exactly; -1032 is exact (Sterbenz)
            uint32_t p0 = 0x64006400u | (uint32_t)q.x | ((uint32_t)q.y << 16);
            uint32_t p1 = 0x64006400u | (uint32_t)q.z | ((uint32_t)q.w << 16);
            __half2 h0 = __hsub2(*reinterpret_cast<const __half2*>(&p0), k1032);
            __half2 h1 = __hsub2(*reinterpret_cast<const __half2*>(&p1), k1032);
            __half2 w0 = __hfma2(h0, s2, z2);   // (q-8)*s + z
            __half2 w1 = __hfma2(h1, s2, z2);
            uint2 pk;
            pk.x = *reinterpret_cast<uint32_t*>(&w0);
            pk.y = *reinterpret_cast<uint32_t*>(&w1);
            *reinterpret_cast<uint2*>(&Bs[nloc * LDK + lane * 4]) = pk;
        }
        __syncthreads();

        // ---- prefetch next chunk (overlaps with MMA below) ----
        if (c + 1 < NG) {
            const int k0 = (c + 1) * BK;
            #pragma unroll
            for (int it = 0; it < 8; ++it)
                wq[it] = *reinterpret_cast<const int4*>(
                    qw + (size_t)(nblk + it * 8 + warp) * K_IN + k0 + lane * 4);
            #pragma unroll
            for (int it = 0; it < 4; ++it)
                xr[it] = *reinterpret_cast<const int4*>(
                    g_xh + (size_t)(it * 16 + (tid >> 4)) * K_IN + k0 + (tid & 15) * 8);
        }

        // ---- MMA: 8 k-steps of m16n8k16, 4 n-atoms per warp ----
        #pragma unroll
        for (int kk = 0; kk < 8; ++kk) {
            uint32_t a0, a1, a2, a3;
            ldsm4(a0, a1, a2, a3, a_off + kk * 32);
            uint32_t b0, b1, b2, b3, b4, b5, b6, b7;
            ldsm4(b0, b1, b2, b3, b_off0 + kk * 32);
            ldsm4(b4, b5, b6, b7, b_off1 + kk * 32);
            mma_16816(acc[0], a0, a1, a2, a3, b0, b1);
            mma_16816(acc[1], a0, a1, a2, a3, b2, b3);
            mma_16816(acc[2], a0, a1, a2, a3, b4, b5);
            mma_16816(acc[3], a0, a1, a2, a3, b6, b7);
        }
        __syncthreads();
    }

    // ---- epilogue: fp32 stores, 2 float2 per n-atom ----
    const int row = wm * 16 + (lane >> 2);
    #pragma unroll
    for (int j = 0; j < 4; ++j) {
        const int col = nblk + wn * 32 + j * 8 + (lane & 3) * 2;
        float2 v0 = make_float2(acc[j][0], acc[j][1]);
        float2 v1 = make_float2(acc[j][2], acc[j][3]);
        *reinterpret_cast<float2*>(out + (size_t)row * N_OUT + col)       = v0;
        *reinterpret_cast<float2*>(out + (size_t)(row + 8) * N_OUT + col) = v1;
    }
}

extern "C" void kernel_launch(void* const* d_in, const int* in_sizes, int n_in,
                              void* d_out, int out_size) {
    const float* x  = (const float*)d_in[0];   // (64, 8192) fp32
    const int*   qw = (const int*)d_in[1];     // (8192, 8192) int32 in [0,15]
    const float* sz = (const float*)d_in[2];   // (64, 8192, 2) fp32
    float* out = (float*)d_out;                // (64, 8192) fp32

    convert_x_kernel<<<(M_TOK * K_IN / 2) / NTHREADS, NTHREADS>>>(x);
    woq_gemm_kernel<<<N_OUT / BN, NTHREADS>>>(qw, sz, out);
}

// round 2
// speedup vs baseline: 1.2476x; 1.2476x over previous
#include <cuda_runtime.h>
#include <cuda_fp16.h>
#include <cstdint>

#define M_TOK 64
#define N_OUT 8192
#define K_IN  8192
#define NG    64          // total K groups (8192/128)
#define NSPLIT 2          // split-K factor
#define NGH   (NG / NSPLIT)
#define BN    64          // N columns per block
#define BK    128         // K per chunk == quant group size
#define LDK   136         // smem row stride in halves (conflict-free ldmatrix)
#define NTHREADS 256

// x pre-converted to fp16 (1 MB, L2-resident)
__device__ __half g_xh[M_TOK * K_IN];
// split-K partials (4 MB)
__device__ float g_part[NSPLIT][M_TOK * N_OUT];

__global__ void convert_x_kernel(const float* __restrict__ x) {
    int i = (blockIdx.x * blockDim.x + threadIdx.x) * 2;
    float2 v = *reinterpret_cast<const float2*>(x + i);
    *reinterpret_cast<__half2*>(g_xh + i) = __floats2half2_rn(v.x, v.y);
}

__global__ void reduce_kernel(float* __restrict__ out) {
    int i = (blockIdx.x * blockDim.x + threadIdx.x) * 4;
    float4 a = *reinterpret_cast<const float4*>(&g_part[0][i]);
    float4 b = *reinterpret_cast<const float4*>(&g_part[1][i]);
    a.x += b.x; a.y += b.y; a.z += b.z; a.w += b.w;
    *reinterpret_cast<float4*>(out + i) = a;
}

__device__ __forceinline__ void ldsm4(uint32_t& r0, uint32_t& r1, uint32_t& r2, uint32_t& r3,
                                      uint32_t a) {
    asm volatile("ldmatrix.sync.aligned.m8n8.x4.shared.b16 {%0,%1,%2,%3}, [%4];"
                 : "=r"(r0), "=r"(r1), "=r"(r2), "=r"(r3) : "r"(a));
}

__device__ __forceinline__ void mma_16816(float c[4],
                                          uint32_t a0, uint32_t a1, uint32_t a2, uint32_t a3,
                                          uint32_t b0, uint32_t b1) {
    asm volatile("mma.sync.aligned.m16n8k16.row.col.f32.f16.f16.f32 "
                 "{%0,%1,%2,%3}, {%4,%5,%6,%7}, {%8,%9}, {%0,%1,%2,%3};"
                 : "+f"(c[0]), "+f"(c[1]), "+f"(c[2]), "+f"(c[3])
                 : "r"(a0), "r"(a1), "r"(a2), "r"(a3), "r"(b0), "r"(b1));
}

__global__ void __launch_bounds__(NTHREADS, 2)
woq_gemm_kernel(const int* __restrict__ qw,      // [N_OUT][K_IN] int32, values 0..15
                const float* __restrict__ sz)    // [NG][N_OUT][2] (scale, zero_point)
{
    __shared__ __half As[M_TOK * LDK];  // x tile   [64][BK]
    __shared__ __half Bs[BN * LDK];     // w tile   [64][BK] (dequantized fp16)

    const int tid  = threadIdx.x;
    const int lane = tid & 31;
    const int warp = tid >> 5;
    const int wm   = warp & 3;   // m-tile of 16 rows
    const int wn   = warp >> 2;  // n-half of 32 cols
    const int nblk = blockIdx.x * BN;
    const int kz   = blockIdx.y;           // split-K index
    const int g0   = kz * NGH;             // first group of this split

    float acc[4][4];
    #pragma unroll
    for (int i = 0; i < 4; ++i)
        #pragma unroll
        for (int j = 0; j < 4; ++j) acc[i][j] = 0.f;

    const uint32_t as_b = (uint32_t)__cvta_generic_to_shared(As);
    const uint32_t bs_b = (uint32_t)__cvta_generic_to_shared(Bs);

    const uint32_t a_off  = as_b + 2u * ((wm * 16 + (lane & 15)) * LDK + (lane >> 4) * 8);
    const uint32_t b_off0 = bs_b + 2u * ((wn * 32 + (lane & 7) + ((lane >> 4) << 3)) * LDK
                                         + ((lane >> 3) & 1) * 8);
    const uint32_t b_off1 = b_off0 + 2u * 16 * LDK;

    int4 wq[8];   // staged int32 weights: 32 q values/thread/chunk
    int4 xr[4];   // staged x halves:      32 halves/thread/chunk

    // ---- prologue: load first chunk of this split ----
    {
        const int k0 = g0 * BK;
        #pragma unroll
        for (int it = 0; it < 8; ++it)
            wq[it] = *reinterpret_cast<const int4*>(
                qw + (size_t)(nblk + it * 8 + warp) * K_IN + k0 + lane * 4);
        #pragma unroll
        for (int it = 0; it < 4; ++it)
            xr[it] = *reinterpret_cast<const int4*>(
                g_xh + (size_t)(it * 16 + (tid >> 4)) * K_IN + k0 + (tid & 15) * 8);
    }

    const __half2 k1032 = __floats2half2_rn(1032.f, 1032.f);  // exact in fp16

    for (int c = 0; c < NGH; ++c) {
        const int g = g0 + c;
        // ---- stage x tile ----
        #pragma unroll
        for (int it = 0; it < 4; ++it)
            *reinterpret_cast<int4*>(&As[(it * 16 + (tid >> 4)) * LDK + (tid & 15) * 8]) = xr[it];

        // ---- dequant + stage w tile ----
        #pragma unroll
        for (int it = 0; it < 8; ++it) {
            const int nloc = it * 8 + warp;
            float2 s_z = *reinterpret_cast<const float2*>(
                sz + 2u * ((size_t)g * N_OUT + nblk + nloc));
            const __half2 s2 = __half2half2(__float2half_rn(s_z.x));
            const __half2 z2 = __half2half2(__float2half_rn(s_z.y));
            const int4 q = wq[it];
            uint32_t p0 = 0x64006400u | (uint32_t)q.x | ((uint32_t)q.y << 16);
            uint32_t p1 = 0x64006400u | (uint32_t)q.z | ((uint32_t)q.w << 16);
            __half2 h0 = __hsub2(*reinterpret_cast<const __half2*>(&p0), k1032);
            __half2 h1 = __hsub2(*reinterpret_cast<const __half2*>(&p1), k1032);
            __half2 w0 = __hfma2(h0, s2, z2);   // (q-8)*s + z
            __half2 w1 = __hfma2(h1, s2, z2);
            uint2 pk;
            pk.x = *reinterpret_cast<uint32_t*>(&w0);
            pk.y = *reinterpret_cast<uint32_t*>(&w1);
            *reinterpret_cast<uint2*>(&Bs[nloc * LDK + lane * 4]) = pk;
        }
        __syncthreads();

        // ---- prefetch next chunk (overlaps with MMA below) ----
        if (c + 1 < NGH) {
            const int k0 = (g + 1) * BK;
            #pragma unroll
            for (int it = 0; it < 8; ++it)
                wq[it] = *reinterpret_cast<const int4*>(
                    qw + (size_t)(nblk + it * 8 + warp) * K_IN + k0 + lane * 4);
            #pragma unroll
            for (int it = 0; it < 4; ++it)
                xr[it] = *reinterpret_cast<const int4*>(
                    g_xh + (size_t)(it * 16 + (tid >> 4)) * K_IN + k0 + (tid & 15) * 8);
        }

        // ---- MMA: 8 k-steps of m16n8k16, 4 n-atoms per warp ----
        #pragma unroll
        for (int kk = 0; kk < 8; ++kk) {
            uint32_t a0, a1, a2, a3;
            ldsm4(a0, a1, a2, a3, a_off + kk * 32);
            uint32_t b0, b1, b2, b3, b4, b5, b6, b7;
            ldsm4(b0, b1, b2, b3, b_off0 + kk * 32);
            ldsm4(b4, b5, b6, b7, b_off1 + kk * 32);
            mma_16816(acc[0], a0, a1, a2, a3, b0, b1);
            mma_16816(acc[1], a0, a1, a2, a3, b2, b3);
            mma_16816(acc[2], a0, a1, a2, a3, b4, b5);
            mma_16816(acc[3], a0, a1, a2, a3, b6, b7);
        }
        __syncthreads();
    }

    // ---- epilogue: write split-K partials ----
    float* part = g_part[kz];
    const int row = wm * 16 + (lane >> 2);
    #pragma unroll
    for (int j = 0; j < 4; ++j) {
        const int col = nblk + wn * 32 + j * 8 + (lane & 3) * 2;
        float2 v0 = make_float2(acc[j][0], acc[j][1]);
        float2 v1 = make_float2(acc[j][2], acc[j][3]);
        *reinterpret_cast<float2*>(part + (size_t)row * N_OUT + col)       = v0;
        *reinterpret_cast<float2*>(part + (size_t)(row + 8) * N_OUT + col) = v1;
    }
}

extern "C" void kernel_launch(void* const* d_in, const int* in_sizes, int n_in,
                              void* d_out, int out_size) {
    const float* x  = (const float*)d_in[0];   // (64, 8192) fp32
    const int*   qw = (const int*)d_in[1];     // (8192, 8192) int32 in [0,15]
    const float* sz = (const float*)d_in[2];   // (64, 8192, 2) fp32
    float* out = (float*)d_out;                // (64, 8192) fp32

    convert_x_kernel<<<(M_TOK * K_IN / 2) / NTHREADS, NTHREADS>>>(x);
    dim3 grid(N_OUT / BN, NSPLIT);
    woq_gemm_kernel<<<grid, NTHREADS>>>(qw, sz);
    reduce_kernel<<<(M_TOK * N_OUT / 4) / NTHREADS, NTHREADS>>>(out);
}

// round 3
// speedup vs baseline: 1.3843x; 1.1096x over previous
#include <cuda_runtime.h>
#include <cuda_fp16.h>
#include <cstdint>

#define M_TOK 64
#define N_OUT 8192
#define K_IN  8192
#define NG    64          // total K groups (8192/128)
#define NSPLIT 2          // split-K factor
#define NGH   (NG / NSPLIT)
#define BN    64          // N columns per block
#define BK    128         // K per chunk == quant group size
#define LDK   136         // smem row stride in halves (conflict-free ldmatrix)
#define NTHREADS 256
#define ABYTES (M_TOK * LDK * 2)          // 17408 B per As buffer
#define BBYTES (BN * LDK * 2)             // 17408 B per Bs buffer
#define SMEM_BYTES (2 * ABYTES + 2 * BBYTES)  // 69632 B

// x pre-converted to fp16 (1 MB, L2-resident)
__device__ __half g_xh[M_TOK * K_IN];
// scale/zero pre-packed as half2 (lo=s, hi=z), 2 MB
__device__ uint32_t g_szp[NG * N_OUT];
// split-K partials (4 MB)
__device__ float g_part[NSPLIT][M_TOK * N_OUT];

// ---- fused prep: convert x to fp16 + pack (s,z) to half2 ----
__global__ void prep_kernel(const float* __restrict__ x, const float* __restrict__ sz) {
    const int NX = M_TOK * K_IN / 4;  // 131072 threads for x
    int t = blockIdx.x * blockDim.x + threadIdx.x;
    if (t < NX) {
        float4 v = *reinterpret_cast<const float4*>(x + (size_t)t * 4);
        __half2 h0 = __floats2half2_rn(v.x, v.y);
        __half2 h1 = __floats2half2_rn(v.z, v.w);
        uint2 pk;
        pk.x = *reinterpret_cast<uint32_t*>(&h0);
        pk.y = *reinterpret_cast<uint32_t*>(&h1);
        *reinterpret_cast<uint2*>(g_xh + (size_t)t * 4) = pk;
    } else {
        int u = t - NX;  // 0 .. NG*N_OUT/2-1
        float4 v = *reinterpret_cast<const float4*>(sz + (size_t)u * 4);
        __half2 a = __floats2half2_rn(v.x, v.y);  // (s0, z0)
        __half2 b = __floats2half2_rn(v.z, v.w);  // (s1, z1)
        uint2 pk;
        pk.x = *reinterpret_cast<uint32_t*>(&a);
        pk.y = *reinterpret_cast<uint32_t*>(&b);
        *reinterpret_cast<uint2*>(g_szp + (size_t)u * 2) = pk;
    }
}

__global__ void reduce_kernel(float* __restrict__ out) {
    int i = (blockIdx.x * blockDim.x + threadIdx.x) * 8;
    float4 a0 = *reinterpret_cast<const float4*>(&g_part[0][i]);
    float4 a1 = *reinterpret_cast<const float4*>(&g_part[0][i + 4]);
    float4 b0 = *reinterpret_cast<const float4*>(&g_part[1][i]);
    float4 b1 = *reinterpret_cast<const float4*>(&g_part[1][i + 4]);
    a0.x += b0.x; a0.y += b0.y; a0.z += b0.z; a0.w += b0.w;
    a1.x += b1.x; a1.y += b1.y; a1.z += b1.z; a1.w += b1.w;
    *reinterpret_cast<float4*>(out + i)     = a0;
    *reinterpret_cast<float4*>(out + i + 4) = a1;
}

__device__ __forceinline__ void cp16(uint32_t dst, const void* src) {
    asm volatile("cp.async.cg.shared.global [%0], [%1], 16;" :: "r"(dst), "l"(src));
}

__device__ __forceinline__ void ldsm4(uint32_t& r0, uint32_t& r1, uint32_t& r2, uint32_t& r3,
                                      uint32_t a) {
    asm volatile("ldmatrix.sync.aligned.m8n8.x4.shared.b16 {%0,%1,%2,%3}, [%4];"
                 : "=r"(r0), "=r"(r1), "=r"(r2), "=r"(r3) : "r"(a));
}

__device__ __forceinline__ void mma_16816(float c[4],
                                          uint32_t a0, uint32_t a1, uint32_t a2, uint32_t a3,
                                          uint32_t b0, uint32_t b1) {
    asm volatile("mma.sync.aligned.m16n8k16.row.col.f32.f16.f16.f32 "
                 "{%0,%1,%2,%3}, {%4,%5,%6,%7}, {%8,%9}, {%0,%1,%2,%3};"
                 : "+f"(c[0]), "+f"(c[1]), "+f"(c[2]), "+f"(c[3])
                 : "r"(a0), "r"(a1), "r"(a2), "r"(a3), "r"(b0), "r"(b1));
}

__global__ void __launch_bounds__(NTHREADS, 2)
woq_gemm_kernel(const int* __restrict__ qw)      // [N_OUT][K_IN] int32, values 0..15
{
    extern __shared__ __half smem[];
    __half* Bs = smem + 2 * M_TOK * LDK;  // after the two As buffers

    const int tid  = threadIdx.x;
    const int lane = tid & 31;
    const int warp = tid >> 5;
    const int wm   = warp & 3;   // m-tile of 16 rows
    const int wn   = warp >> 2;  // n-half of 32 cols
    const int nblk = blockIdx.x * BN;
    const int kz   = blockIdx.y;           // split-K index
    const int g0   = kz * NGH;             // first group of this split

    float acc[4][4];
    #pragma unroll
    for (int i = 0; i < 4; ++i)
        #pragma unroll
        for (int j = 0; j < 4; ++j) acc[i][j] = 0.f;

    const uint32_t s_base = (uint32_t)__cvta_generic_to_shared(smem);
    const uint32_t as_b = s_base;
    const uint32_t bs_b = s_base + 2 * ABYTES;

    // ldmatrix lane addressing within a buffer (add buf*ABYTES / buf*BBYTES)
    const uint32_t a_off  = as_b + 2u * ((wm * 16 + (lane & 15)) * LDK + (lane >> 4) * 8);
    const uint32_t b_off0 = bs_b + 2u * ((wn * 32 + (lane & 7) + ((lane >> 4) << 3)) * LDK
                                         + ((lane >> 3) & 1) * 8);
    const uint32_t b_off1 = b_off0 + 2u * 16 * LDK;

    // cp.async mapping for the x tile: 1024 16B-units; thread t does 4
    const int xrow0 = tid >> 4;   // 0..15
    const int xcol  = tid & 15;   // 0..15 (16B columns)
    const __half* xsrc = g_xh + (size_t)xrow0 * K_IN + xcol * 8;
    const uint32_t adst = as_b + 2u * (xrow0 * LDK + xcol * 8);

    int4     wq[8];   // staged int32 weights: 32 q values/thread/chunk
    uint32_t szr[8];  // staged packed (s,z) half2 per owned row

    const int* qrow = qw + (size_t)(nblk + warp) * K_IN + lane * 4;
    const uint32_t* szrow = g_szp + nblk + warp;

    // ---- prologue: chunk g0 ----
    {
        const int k0 = g0 * BK;
        #pragma unroll
        for (int j = 0; j < 4; ++j)
            cp16(adst + j * (16 * LDK * 2), xsrc + (size_t)j * 16 * K_IN + k0);
        asm volatile("cp.async.commit_group;");
        #pragma unroll
        for (int it = 0; it < 8; ++it)
            wq[it] = *reinterpret_cast<const int4*>(qrow + (size_t)(it * 8) * K_IN + k0);
        #pragma unroll
        for (int it = 0; it < 8; ++it)
            szr[it] = szrow[(size_t)g0 * N_OUT + it * 8];
    }

    const __half2 k1032 = __floats2half2_rn(1032.f, 1032.f);  // exact in fp16

    for (int c = 0; c < NGH; ++c) {
        const int buf = c & 1;
        asm volatile("cp.async.wait_group 0;");

        // ---- dequant + stage w tile into Bs[buf] ----
        __half* Bsb = Bs + buf * (BN * LDK);
        #pragma unroll
        for (int it = 0; it < 8; ++it) {
            const int nloc = it * 8 + warp;
            const __half2 szh = *reinterpret_cast<const __half2*>(&szr[it]);
            const __half2 s2 = __half2half2(__low2half(szh));
            const __half2 z2 = __half2half2(__high2half(szh));
            const int4 q = wq[it];
            uint32_t p0 = 0x64006400u | (uint32_t)q.x | ((uint32_t)q.y << 16);
            uint32_t p1 = 0x64006400u | (uint32_t)q.z | ((uint32_t)q.w << 16);
            __half2 h0 = __hsub2(*reinterpret_cast<const __half2*>(&p0), k1032);
            __half2 h1 = __hsub2(*reinterpret_cast<const __half2*>(&p1), k1032);
            __half2 w0 = __hfma2(h0, s2, z2);   // (q-8)*s + z
            __half2 w1 = __hfma2(h1, s2, z2);
            uint2 pk;
            pk.x = *reinterpret_cast<uint32_t*>(&w0);
            pk.y = *reinterpret_cast<uint32_t*>(&w1);
            *reinterpret_cast<uint2*>(&Bsb[nloc * LDK + lane * 4]) = pk;
        }

        // Single barrier per chunk: publishes Bs[buf] STS + As[buf] cp.async,
        // and guarantees all warps finished MMA(c-1) before we overwrite
        // As[buf^1] / issue next prefetch.
        __syncthreads();

        // ---- prefetch chunk c+1 (overlaps with MMA below) ----
        if (c + 1 < NGH) {
            const int g1 = g0 + c + 1;
            const int k0 = g1 * BK;
            #pragma unroll
            for (int j = 0; j < 4; ++j)
                cp16(adst + (buf ^ 1) * ABYTES + j * (16 * LDK * 2),
                     xsrc + (size_t)j * 16 * K_IN + k0);
            asm volatile("cp.async.commit_group;");
            #pragma unroll
            for (int it = 0; it < 8; ++it)
                wq[it] = *reinterpret_cast<const int4*>(qrow + (size_t)(it * 8) * K_IN + k0);
            #pragma unroll
            for (int it = 0; it < 8; ++it)
                szr[it] = szrow[(size_t)g1 * N_OUT + it * 8];
        }

        // ---- MMA: 8 k-steps of m16n8k16, 4 n-atoms per warp ----
        const uint32_t ab = a_off  + buf * ABYTES;
        const uint32_t bb0 = b_off0 + buf * BBYTES;
        const uint32_t bb1 = b_off1 + buf * BBYTES;
        #pragma unroll
        for (int kk = 0; kk < 8; ++kk) {
            uint32_t a0, a1, a2, a3;
            ldsm4(a0, a1, a2, a3, ab + kk * 32);
            uint32_t b0, b1, b2, b3, b4, b5, b6, b7;
            ldsm4(b0, b1, b2, b3, bb0 + kk * 32);
            ldsm4(b4, b5, b6, b7, bb1 + kk * 32);
            mma_16816(acc[0], a0, a1, a2, a3, b0, b1);
            mma_16816(acc[1], a0, a1, a2, a3, b2, b3);
            mma_16816(acc[2], a0, a1, a2, a3, b4, b5);
            mma_16816(acc[3], a0, a1, a2, a3, b6, b7);
        }
        // no trailing barrier: next iteration writes only the other buffers
    }

    // ---- epilogue: write split-K partials ----
    float* part = g_part[kz];
    const int row = wm * 16 + (lane >> 2);
    #pragma unroll
    for (int j = 0; j < 4; ++j) {
        const int col = nblk + wn * 32 + j * 8 + (lane & 3) * 2;
        float2 v0 = make_float2(acc[j][0], acc[j][1]);
        float2 v1 = make_float2(acc[j][2], acc[j][3]);
        *reinterpret_cast<float2*>(part + (size_t)row * N_OUT + col)       = v0;
        *reinterpret_cast<float2*>(part + (size_t)(row + 8) * N_OUT + col) = v1;
    }
}

extern "C" void kernel_launch(void* const* d_in, const int* in_sizes, int n_in,
                              void* d_out, int out_size) {
    const float* x  = (const float*)d_in[0];   // (64, 8192) fp32
    const int*   qw = (const int*)d_in[1];     // (8192, 8192) int32 in [0,15]
    const float* sz = (const float*)d_in[2];   // (64, 8192, 2) fp32
    float* out = (float*)d_out;                // (64, 8192) fp32

    static bool attr_set = false;
    if (!attr_set) {
        cudaFuncSetAttribute(woq_gemm_kernel,
                             cudaFuncAttributeMaxDynamicSharedMemorySize, SMEM_BYTES);
        attr_set = true;
    }

    const int n_prep = (M_TOK * K_IN / 4) + (NG * N_OUT / 2);  // 393216 threads
    prep_kernel<<<n_prep / NTHREADS, NTHREADS>>>(x, sz);
    dim3 grid(N_OUT / BN, NSPLIT);
    woq_gemm_kernel<<<grid, NTHREADS, SMEM_BYTES>>>(qw);
    reduce_kernel<<<(M_TOK * N_OUT / 8) / NTHREADS, NTHREADS>>>(out);
}

// round 4
// speedup vs baseline: 1.4796x; 1.0688x over previous
#include <cuda_runtime.h>
#include <cuda_fp16.h>
#include <cstdint>

#define M_TOK 64
#define N_OUT 8192
#define K_IN  8192
#define NG    64            // K groups per row (8192/128)
#define NTILES (N_OUT / 64) // 128
#define WTOTAL (NTILES * NG)// 8192 work units
#define NCTA  296           // 2 per SM on 148 SMs, all resident
#define BN    64
#define BK    128
#define LDK   136
#define NTHREADS 256
#define ABYTES (M_TOK * LDK * 2)
#define BBYTES (BN * LDK * 2)
#define SMEM_BYTES (2 * ABYTES + 2 * BBYTES)  // 69632 B

__device__ __half   g_xh[M_TOK * K_IN];     // x in fp16 (1 MB)
__device__ uint32_t g_szp[NG * N_OUT];      // packed (s,z) half2 (2 MB)
__device__ float    g_part[NCTA * 2 * 4096];// stream-K partials (9.7 MB)

__device__ __forceinline__ int gsplit(int c) { return (int)(((long long)c * WTOTAL) / NCTA); }

// ---- fused prep: convert x to fp16 + pack (s,z) to half2, 8 floats/thread ----
__global__ void prep_kernel(const float* __restrict__ x, const float* __restrict__ sz) {
    const int NX = M_TOK * K_IN / 8;  // 65536 threads for x
    int t = blockIdx.x * blockDim.x + threadIdx.x;
    if (t < NX) {
        float4 v0 = *reinterpret_cast<const float4*>(x + (size_t)t * 8);
        float4 v1 = *reinterpret_cast<const float4*>(x + (size_t)t * 8 + 4);
        __half2 h0 = __floats2half2_rn(v0.x, v0.y);
        __half2 h1 = __floats2half2_rn(v0.z, v0.w);
        __half2 h2 = __floats2half2_rn(v1.x, v1.y);
        __half2 h3 = __floats2half2_rn(v1.z, v1.w);
        uint4 pk;
        pk.x = *reinterpret_cast<uint32_t*>(&h0);
        pk.y = *reinterpret_cast<uint32_t*>(&h1);
        pk.z = *reinterpret_cast<uint32_t*>(&h2);
        pk.w = *reinterpret_cast<uint32_t*>(&h3);
        *reinterpret_cast<uint4*>(g_xh + (size_t)t * 8) = pk;
    } else {
        int u = t - NX;  // 0 .. NG*N_OUT/4-1
        float4 v0 = *reinterpret_cast<const float4*>(sz + (size_t)u * 8);
        float4 v1 = *reinterpret_cast<const float4*>(sz + (size_t)u * 8 + 4);
        __half2 a = __floats2half2_rn(v0.x, v0.y);
        __half2 b = __floats2half2_rn(v0.z, v0.w);
        __half2 cc = __floats2half2_rn(v1.x, v1.y);
        __half2 d = __floats2half2_rn(v1.z, v1.w);
        uint4 pk;
        pk.x = *reinterpret_cast<uint32_t*>(&a);
        pk.y = *reinterpret_cast<uint32_t*>(&b);
        pk.z = *reinterpret_cast<uint32_t*>(&cc);
        pk.w = *reinterpret_cast<uint32_t*>(&d);
        *reinterpret_cast<uint4*>(g_szp + (size_t)u * 4) = pk;
    }
}

// ---- stream-K reduce: fixed contributor set per ntile, deterministic order ----
__global__ void reduce_kernel(float* __restrict__ out) {
    int i2 = (blockIdx.x * blockDim.x + threadIdx.x) * 2;
    int m  = i2 >> 13;          // / 8192
    int n  = i2 & (N_OUT - 1);
    int nt = n >> 6, nl = n & 63;
    int X  = nt << 6;           // first work unit of this ntile
    int c  = (int)(((long long)X * NCTA) >> 13);  // * NCTA / WTOTAL
    while (gsplit(c + 1) <= X) ++c;
    float sx = 0.f, sy = 0.f;
    while (c < NCTA && gsplit(c) < X + 64) {
        int seg = ((gsplit(c) >> 6) == nt) ? 0 : 1;
        const float2 v = *reinterpret_cast<const float2*>(
            g_part + ((size_t)c * 2 + seg) * 4096 + m * 64 + nl);
        sx += v.x; sy += v.y;
        ++c;
    }
    *reinterpret_cast<float2*>(out + i2) = make_float2(sx, sy);
}

__device__ __forceinline__ void cp16(uint32_t dst, const void* src) {
    asm volatile("cp.async.cg.shared.global [%0], [%1], 16;" :: "r"(dst), "l"(src));
}

__device__ __forceinline__ void ldsm4(uint32_t& r0, uint32_t& r1, uint32_t& r2, uint32_t& r3,
                                      uint32_t a) {
    asm volatile("ldmatrix.sync.aligned.m8n8.x4.shared.b16 {%0,%1,%2,%3}, [%4];"
                 : "=r"(r0), "=r"(r1), "=r"(r2), "=r"(r3) : "r"(a));
}

__device__ __forceinline__ void mma_16816(float c[4],
                                          uint32_t a0, uint32_t a1, uint32_t a2, uint32_t a3,
                                          uint32_t b0, uint32_t b1) {
    asm volatile("mma.sync.aligned.m16n8k16.row.col.f32.f16.f16.f32 "
                 "{%0,%1,%2,%3}, {%4,%5,%6,%7}, {%8,%9}, {%0,%1,%2,%3};"
                 : "+f"(c[0]), "+f"(c[1]), "+f"(c[2]), "+f"(c[3])
                 : "r"(a0), "r"(a1), "r"(a2), "r"(a3), "r"(b0), "r"(b1));
}

// load the chunk for work unit w: wq/szp into regs, x tile via cp.async into As[pbuf]
__device__ __forceinline__ void load_chunk(int w, int pbuf,
                                           const int* __restrict__ qw,
                                           int warp, int lane,
                                           const __half* xsrc, uint32_t adst,
                                           int4 wq[8], uint32_t szr[8]) {
    const int g  = w & (NG - 1);
    const int nb = (w >> 6) << 6;    // nblk
    const int k0 = g * BK;
    const int* qr = qw + (size_t)(nb + warp) * K_IN + k0 + lane * 4;
    #pragma unroll
    for (int it = 0; it < 8; ++it)
        wq[it] = *reinterpret_cast<const int4*>(qr + (size_t)(it * 8) * K_IN);
    const uint32_t* szp = g_szp + (size_t)g * N_OUT + nb + warp;
    #pragma unroll
    for (int it = 0; it < 8; ++it)
        szr[it] = szp[it * 8];
    #pragma unroll
    for (int j = 0; j < 4; ++j)
        cp16(adst + pbuf * ABYTES + j * (16 * LDK * 2), xsrc + (size_t)j * 16 * K_IN + k0);
    asm volatile("cp.async.commit_group;");
}

__global__ void __launch_bounds__(NTHREADS, 2)
woq_gemm_kernel(const int* __restrict__ qw)
{
    extern __shared__ __half smem[];
    __half* Bs = smem + 2 * M_TOK * LDK;

    const int tid  = threadIdx.x;
    const int lane = tid & 31;
    const int warp = tid >> 5;
    const int wm   = warp & 3;
    const int wn   = warp >> 2;
    const int cta  = blockIdx.x;

    const int w0 = gsplit(cta);
    const int w1 = gsplit(cta + 1);

    float acc[4][4];
    #pragma unroll
    for (int i = 0; i < 4; ++i)
        #pragma unroll
        for (int j = 0; j < 4; ++j) acc[i][j] = 0.f;

    const uint32_t s_base = (uint32_t)__cvta_generic_to_shared(smem);
    const uint32_t as_b = s_base;
    const uint32_t bs_b = s_base + 2 * ABYTES;

    const uint32_t a_off  = as_b + 2u * ((wm * 16 + (lane & 15)) * LDK + (lane >> 4) * 8);
    const uint32_t b_off0 = bs_b + 2u * ((wn * 32 + (lane & 7) + ((lane >> 4) << 3)) * LDK
                                         + ((lane >> 3) & 1) * 8);
    const uint32_t b_off1 = b_off0 + 2u * 16 * LDK;

    const int xrow0 = tid >> 4;
    const int xcol  = tid & 15;
    const __half* xsrc = g_xh + (size_t)xrow0 * K_IN + xcol * 8;
    const uint32_t adst = as_b + 2u * (xrow0 * LDK + xcol * 8);

    int4     wq[8];
    uint32_t szr[8];

    load_chunk(w0, 0, qw, warp, lane, xsrc, adst, wq, szr);

    const __half2 k1032 = __floats2half2_rn(1032.f, 1032.f);
    int seg = 0;

    for (int w = w0; w < w1; ++w) {
        const int p = (w - w0) & 1;
        asm volatile("cp.async.wait_group 0;");

        // ---- dequant + stage w tile into Bs[p] ----
        __half* Bsb = Bs + p * (BN * LDK);
        #pragma unroll
        for (int it = 0; it < 8; ++it) {
            const int nloc = it * 8 + warp;
            const __half2 szh = *reinterpret_cast<const __half2*>(&szr[it]);
            const __half2 s2 = __half2half2(__low2half(szh));
            const __half2 z2 = __half2half2(__high2half(szh));
            const int4 q = wq[it];
            uint32_t p0 = 0x64006400u | (uint32_t)q.x | ((uint32_t)q.y << 16);
            uint32_t p1 = 0x64006400u | (uint32_t)q.z | ((uint32_t)q.w << 16);
            __half2 h0 = __hsub2(*reinterpret_cast<const __half2*>(&p0), k1032);
            __half2 h1 = __hsub2(*reinterpret_cast<const __half2*>(&p1), k1032);
            __half2 w0h = __hfma2(h0, s2, z2);
            __half2 w1h = __hfma2(h1, s2, z2);
            uint2 pk;
            pk.x = *reinterpret_cast<uint32_t*>(&w0h);
            pk.y = *reinterpret_cast<uint32_t*>(&w1h);
            *reinterpret_cast<uint2*>(&Bsb[nloc * LDK + lane * 4]) = pk;
        }
        __syncthreads();

        // ---- prefetch chunk w+1 (overlaps MMA) ----
        if (w + 1 < w1)
            load_chunk(w + 1, p ^ 1, qw, warp, lane, xsrc, adst, wq, szr);

        // ---- MMA ----
        const uint32_t ab  = a_off  + p * ABYTES;
        const uint32_t bb0 = b_off0 + p * BBYTES;
        const uint32_t bb1 = b_off1 + p * BBYTES;
        #pragma unroll
        for (int kk = 0; kk < 8; ++kk) {
            uint32_t a0, a1, a2, a3;
            ldsm4(a0, a1, a2, a3, ab + kk * 32);
            uint32_t b0, b1, b2, b3, b4, b5, b6, b7;
            ldsm4(b0, b1, b2, b3, bb0 + kk * 32);
            ldsm4(b4, b5, b6, b7, bb1 + kk * 32);
            mma_16816(acc[0], a0, a1, a2, a3, b0, b1);
            mma_16816(acc[1], a0, a1, a2, a3, b2, b3);
            mma_16816(acc[2], a0, a1, a2, a3, b4, b5);
            mma_16816(acc[3], a0, a1, a2, a3, b6, b7);
        }

        // ---- segment boundary: write partial block, reset acc ----
        if (w + 1 == w1 || ((w + 1) >> 6) != (w >> 6)) {
            float* part = g_part + ((size_t)cta * 2 + seg) * 4096;
            const int row = wm * 16 + (lane >> 2);
            #pragma unroll
            for (int j = 0; j < 4; ++j) {
                const int col = wn * 32 + j * 8 + (lane & 3) * 2;
                *reinterpret_cast<float2*>(part + row * 64 + col) =
                    make_float2(acc[j][0], acc[j][1]);
                *reinterpret_cast<float2*>(part + (row + 8) * 64 + col) =
                    make_float2(acc[j][2], acc[j][3]);
                acc[j][0] = acc[j][1] = acc[j][2] = acc[j][3] = 0.f;
            }
            ++seg;
        }
    }
}

extern "C" void kernel_launch(void* const* d_in, const int* in_sizes, int n_in,
                              void* d_out, int out_size) {
    const float* x  = (const float*)d_in[0];   // (64, 8192) fp32
    const int*   qw = (const int*)d_in[1];     // (8192, 8192) int32 in [0,15]
    const float* sz = (const float*)d_in[2];   // (64, 8192, 2) fp32
    float* out = (float*)d_out;                // (64, 8192) fp32

    static bool attr_set = false;
    if (!attr_set) {
        cudaFuncSetAttribute(woq_gemm_kernel,
                             cudaFuncAttributeMaxDynamicSharedMemorySize, SMEM_BYTES);
        attr_set = true;
    }

    const int n_prep = (M_TOK * K_IN / 8) + (NG * N_OUT / 4);  // 196608 threads
    prep_kernel<<<n_prep / NTHREADS, NTHREADS>>>(x, sz);
    woq_gemm_kernel<<<NCTA, NTHREADS, SMEM_BYTES>>>(qw);
    reduce_kernel<<<(M_TOK * N_OUT / 2) / NTHREADS, NTHREADS>>>(out);
}